// round 3
// baseline (speedup 1.0000x reference)
#include <cuda_runtime.h>

#define BATCH 4
#define NTOK 2048
#define DM 512
#define NH 8
#define HD 64

// Scratch (device globals — no allocation allowed)
__device__ float g_q[BATCH * NTOK * DM];
__device__ float g_k[BATCH * NTOK * DM];
__device__ float g_v[BATCH * NTOK * DM];
__device__ float g_ao[BATCH * NTOK * DM];

// ---------------------------------------------------------------------------
// GEMM: C[M,512] = A[M,512] @ W[512,512] + bias   (64x64 tile, BK=32, 4x4 micro)
// ---------------------------------------------------------------------------
__global__ __launch_bounds__(256)
void gemm_bias_kernel(const float* __restrict__ A, const float* __restrict__ W,
                      const float* __restrict__ bias, float* __restrict__ C) {
    __shared__ float AshT[32][68];  // transposed A tile [k][m], padded
    __shared__ float Bsh[32][68];   // B tile [k][n], padded

    const int nb = blockIdx.x * 64;
    const int mb = blockIdx.y * 64;
    const int tx = threadIdx.x;
    const int tr = tx >> 4, tc = tx & 15;
    const int r0 = tr * 4, c0 = tc * 4;

    float acc[4][4] = {};

    for (int k0 = 0; k0 < DM; k0 += 32) {
        // Load A tile 64x32 (coalesced along k), store transposed
        #pragma unroll
        for (int t = tx; t < 512; t += 256) {
            int r = t >> 3;
            int k4 = (t & 7) * 4;
            float4 a4 = *(const float4*)(A + (size_t)(mb + r) * DM + k0 + k4);
            AshT[k4 + 0][r] = a4.x;
            AshT[k4 + 1][r] = a4.y;
            AshT[k4 + 2][r] = a4.z;
            AshT[k4 + 3][r] = a4.w;
        }
        // Load B tile 32x64 (coalesced along n)
        #pragma unroll
        for (int t = tx; t < 512; t += 256) {
            int k = t >> 4;
            int c4 = (t & 15) * 4;
            *(float4*)&Bsh[k][c4] = *(const float4*)(W + (size_t)(k0 + k) * DM + nb + c4);
        }
        __syncthreads();

        #pragma unroll
        for (int k = 0; k < 32; k++) {
            float4 a4 = *(float4*)&AshT[k][r0];
            float4 b4 = *(float4*)&Bsh[k][c0];
            float a[4] = {a4.x, a4.y, a4.z, a4.w};
            float b[4] = {b4.x, b4.y, b4.z, b4.w};
            #pragma unroll
            for (int i = 0; i < 4; i++)
                #pragma unroll
                for (int j = 0; j < 4; j++)
                    acc[i][j] += a[i] * b[j];
        }
        __syncthreads();
    }

    float4 bi = *(const float4*)(bias + nb + c0);
    #pragma unroll
    for (int i = 0; i < 4; i++) {
        float4 o;
        o.x = acc[i][0] + bi.x;
        o.y = acc[i][1] + bi.y;
        o.z = acc[i][2] + bi.z;
        o.w = acc[i][3] + bi.w;
        *(float4*)(C + (size_t)(mb + r0 + i) * DM + nb + c0) = o;
    }
}

// ---------------------------------------------------------------------------
// Flash-style masked attention, fp32.
// Grid: (NTOK/64, NH, BATCH).  64-query x 64-key tiles, HD=64.
// smem: Qsh[64][68] | buf[64][68] (K^T, then P) | Vsh[64][64]
// ---------------------------------------------------------------------------
__global__ __launch_bounds__(256)
void attn_kernel(const float* __restrict__ adj) {
    extern __shared__ float sm[];
    float* Qsh = sm;                 // [64][68] : Q[i][d]
    float* buf = sm + 64 * 68;       // [64][68] : K^T[d][j], later P[i][j]
    float* Vsh = sm + 2 * 64 * 68;   // [64][64] : V[j][c]

    const int qt = blockIdx.x;
    const int h  = blockIdx.y;
    const int b  = blockIdx.z;
    const int tx = threadIdx.x;
    const int tr = tx >> 4, tc = tx & 15;
    const int r0 = tr * 4, c0 = tc * 4;
    const int qbase = qt * 64;

    // Load Q tile (rows qbase..qbase+63, head slice h)
    for (int t = tx; t < 64 * 16; t += 256) {
        int r = t >> 4;
        int c4 = (t & 15) * 4;
        float4 v = *(const float4*)(g_q + (size_t)(b * NTOK + qbase + r) * DM + h * HD + c4);
        *(float4*)&Qsh[r * 68 + c4] = v;
    }

    float acc[4][4] = {};
    float m_i[4], l_i[4];
    #pragma unroll
    for (int i = 0; i < 4; i++) { m_i[i] = -1e30f; l_i[i] = 0.0f; }

    for (int kt = 0; kt < NTOK / 64; kt++) {
        const int kbase = kt * 64;
        __syncthreads();  // protect buf/Vsh from previous iteration's readers

        // Load K tile transposed into buf, V tile into Vsh
        for (int t = tx; t < 64 * 16; t += 256) {
            int j = t >> 4;
            int c4 = (t & 15) * 4;
            float4 kv = *(const float4*)(g_k + (size_t)(b * NTOK + kbase + j) * DM + h * HD + c4);
            buf[(c4 + 0) * 68 + j] = kv.x;
            buf[(c4 + 1) * 68 + j] = kv.y;
            buf[(c4 + 2) * 68 + j] = kv.z;
            buf[(c4 + 3) * 68 + j] = kv.w;
            float4 vv = *(const float4*)(g_v + (size_t)(b * NTOK + kbase + j) * DM + h * HD + c4);
            *(float4*)&Vsh[j * 64 + c4] = vv;
        }
        __syncthreads();

        // S = Q @ K^T (4x4 micro-tile per thread)
        float s[4][4] = {};
        #pragma unroll
        for (int d = 0; d < 64; d += 4) {
            float qreg[4][4];
            #pragma unroll
            for (int i = 0; i < 4; i++) {
                float4 t4 = *(float4*)&Qsh[(r0 + i) * 68 + d];
                qreg[i][0] = t4.x; qreg[i][1] = t4.y; qreg[i][2] = t4.z; qreg[i][3] = t4.w;
            }
            float kreg[4][4];
            #pragma unroll
            for (int dd = 0; dd < 4; dd++) {
                float4 t4 = *(float4*)&buf[(d + dd) * 68 + c0];
                kreg[dd][0] = t4.x; kreg[dd][1] = t4.y; kreg[dd][2] = t4.z; kreg[dd][3] = t4.w;
            }
            #pragma unroll
            for (int i = 0; i < 4; i++)
                #pragma unroll
                for (int j = 0; j < 4; j++)
                    #pragma unroll
                    for (int dd = 0; dd < 4; dd++)
                        s[i][j] += qreg[i][dd] * kreg[dd][j];
        }

        // Scale + adjacency mask + online softmax update
        #pragma unroll
        for (int i = 0; i < 4; i++) {
            float4 a4 = *(const float4*)(adj + (size_t)(qbase + r0 + i) * NTOK + kbase + c0);
            s[i][0] = s[i][0] * 0.125f + (a4.x - 1.0f) * 1e9f;
            s[i][1] = s[i][1] * 0.125f + (a4.y - 1.0f) * 1e9f;
            s[i][2] = s[i][2] * 0.125f + (a4.z - 1.0f) * 1e9f;
            s[i][3] = s[i][3] * 0.125f + (a4.w - 1.0f) * 1e9f;

            float mx = fmaxf(fmaxf(s[i][0], s[i][1]), fmaxf(s[i][2], s[i][3]));
            // row reduction across 16 lanes (half-warp owns one row group)
            #pragma unroll
            for (int off = 8; off > 0; off >>= 1)
                mx = fmaxf(mx, __shfl_xor_sync(0xffffffffu, mx, off));

            float mnew = fmaxf(m_i[i], mx);
            float scale = __expf(m_i[i] - mnew);
            m_i[i] = mnew;

            float rs = 0.0f;
            #pragma unroll
            for (int j = 0; j < 4; j++) {
                s[i][j] = __expf(s[i][j] - mnew);
                rs += s[i][j];
            }
            #pragma unroll
            for (int off = 8; off > 0; off >>= 1)
                rs += __shfl_xor_sync(0xffffffffu, rs, off);

            l_i[i] = l_i[i] * scale + rs;
            #pragma unroll
            for (int c = 0; c < 4; c++)
                acc[i][c] *= scale;
        }

        // Stage P into buf (reusing K^T space)
        __syncthreads();
        #pragma unroll
        for (int i = 0; i < 4; i++) {
            float4 p4;
            p4.x = s[i][0]; p4.y = s[i][1]; p4.z = s[i][2]; p4.w = s[i][3];
            *(float4*)&buf[(r0 + i) * 68 + c0] = p4;
        }
        __syncthreads();

        // acc += P @ V
        #pragma unroll
        for (int j = 0; j < 64; j += 4) {
            float preg[4][4];
            #pragma unroll
            for (int i = 0; i < 4; i++) {
                float4 t4 = *(float4*)&buf[(r0 + i) * 68 + j];
                preg[i][0] = t4.x; preg[i][1] = t4.y; preg[i][2] = t4.z; preg[i][3] = t4.w;
            }
            float vreg[4][4];
            #pragma unroll
            for (int jj = 0; jj < 4; jj++) {
                float4 t4 = *(float4*)&Vsh[(j + jj) * 64 + c0];
                vreg[jj][0] = t4.x; vreg[jj][1] = t4.y; vreg[jj][2] = t4.z; vreg[jj][3] = t4.w;
            }
            #pragma unroll
            for (int i = 0; i < 4; i++)
                #pragma unroll
                for (int c = 0; c < 4; c++)
                    #pragma unroll
                    for (int jj = 0; jj < 4; jj++)
                        acc[i][c] += preg[i][jj] * vreg[jj][c];
        }
    }

    // Epilogue: normalize and store to g_ao (layout (b, n, h*64+c) == (b,n,d))
    #pragma unroll
    for (int i = 0; i < 4; i++) {
        float inv = 1.0f / l_i[i];
        float4 o;
        o.x = acc[i][0] * inv;
        o.y = acc[i][1] * inv;
        o.z = acc[i][2] * inv;
        o.w = acc[i][3] * inv;
        *(float4*)(g_ao + (size_t)(b * NTOK + qbase + r0 + i) * DM + h * HD + c0) = o;
    }
}

// ---------------------------------------------------------------------------
extern "C" void kernel_launch(void* const* d_in, const int* in_sizes, int n_in,
                              void* d_out, int out_size) {
    const float* x   = (const float*)d_in[0];
    const float* adj = (const float*)d_in[1];
    const float* Wq  = (const float*)d_in[2];
    const float* bq  = (const float*)d_in[3];
    const float* Wk  = (const float*)d_in[4];
    const float* bk  = (const float*)d_in[5];
    const float* Wv  = (const float*)d_in[6];
    const float* bv  = (const float*)d_in[7];
    const float* Wo  = (const float*)d_in[8];
    const float* bo  = (const float*)d_in[9];
    float* out = (float*)d_out;

    float *pq, *pk, *pv, *pao;
    cudaGetSymbolAddress((void**)&pq, g_q);
    cudaGetSymbolAddress((void**)&pk, g_k);
    cudaGetSymbolAddress((void**)&pv, g_v);
    cudaGetSymbolAddress((void**)&pao, g_ao);

    dim3 gg(DM / 64, BATCH * NTOK / 64);
    gemm_bias_kernel<<<gg, 256>>>(x, Wq, bq, pq);
    gemm_bias_kernel<<<gg, 256>>>(x, Wk, bk, pk);
    gemm_bias_kernel<<<gg, 256>>>(x, Wv, bv, pv);

    const int attn_smem = (2 * 64 * 68 + 64 * 64) * sizeof(float);  // 51200 B
    cudaFuncSetAttribute(attn_kernel, cudaFuncAttributeMaxDynamicSharedMemorySize, attn_smem);
    attn_kernel<<<dim3(NTOK / 64, NH, BATCH), 256, attn_smem>>>(adj);

    gemm_bias_kernel<<<gg, 256>>>(pao, Wo, bo, out);
}

// round 7
// speedup vs baseline: 1.6199x; 1.6199x over previous
#include <cuda_runtime.h>
#include <cuda_bf16.h>

#define BATCH 4
#define NTOK 2048
#define DM 512
#define NH 8
#define HD 64

// ---------------- scratch (device globals; no allocations allowed) ----------
__device__ float g_v [BATCH * NTOK * DM];           // V fp32 (GEMM out)
__device__ float g_ao[BATCH * NTOK * DM];           // attention out fp32
__device__ unsigned short g_qhi[BATCH * NTOK * DM]; // Q bf16 hi/lo, [b][n][D]
__device__ unsigned short g_qlo[BATCH * NTOK * DM];
__device__ unsigned short g_khi[BATCH * NTOK * DM]; // K bf16 hi/lo, [b][n][D]
__device__ unsigned short g_klo[BATCH * NTOK * DM];
__device__ unsigned short g_vthi[BATCH * NTOK * DM]; // V^T bf16, [b][h][d][n]
__device__ unsigned short g_vtlo[BATCH * NTOK * DM];

// ---------------- helpers ---------------------------------------------------
__device__ __forceinline__ unsigned packbf(float lo, float hi) {
    unsigned r;
    asm("cvt.rn.bf16x2.f32 %0, %1, %2;" : "=r"(r) : "f"(hi), "f"(lo));
    return r;  // low 16 bits = bf16(lo), high = bf16(hi)
}

__device__ __forceinline__ void mma16816(float* c,
                                         unsigned a0, unsigned a1, unsigned a2, unsigned a3,
                                         unsigned b0, unsigned b1) {
    asm volatile(
        "mma.sync.aligned.m16n8k16.row.col.f32.bf16.bf16.f32 "
        "{%0,%1,%2,%3}, {%4,%5,%6,%7}, {%8,%9}, {%0,%1,%2,%3};"
        : "+f"(c[0]), "+f"(c[1]), "+f"(c[2]), "+f"(c[3])
        : "r"(a0), "r"(a1), "r"(a2), "r"(a3), "r"(b0), "r"(b1));
}

// ---------------------------------------------------------------------------
// fp32 GEMM: C[M,512] = A @ W + bias   (64x64 tile, BK=32, 4x4 micro)
// ---------------------------------------------------------------------------
__global__ __launch_bounds__(256)
void gemm_bias_kernel(const float* __restrict__ A, const float* __restrict__ W,
                      const float* __restrict__ bias, float* __restrict__ C) {
    __shared__ float AshT[32][68];
    __shared__ float Bsh[32][68];

    const int nb = blockIdx.x * 64;
    const int mb = blockIdx.y * 64;
    const int tx = threadIdx.x;
    const int tr = tx >> 4, tc = tx & 15;
    const int r0 = tr * 4, c0 = tc * 4;

    float acc[4][4] = {};

    for (int k0 = 0; k0 < DM; k0 += 32) {
        #pragma unroll
        for (int t = tx; t < 512; t += 256) {
            int r = t >> 3;
            int k4 = (t & 7) * 4;
            float4 a4 = *(const float4*)(A + (size_t)(mb + r) * DM + k0 + k4);
            AshT[k4 + 0][r] = a4.x;
            AshT[k4 + 1][r] = a4.y;
            AshT[k4 + 2][r] = a4.z;
            AshT[k4 + 3][r] = a4.w;
        }
        #pragma unroll
        for (int t = tx; t < 512; t += 256) {
            int k = t >> 4;
            int c4 = (t & 15) * 4;
            *(float4*)&Bsh[k][c4] = *(const float4*)(W + (size_t)(k0 + k) * DM + nb + c4);
        }
        __syncthreads();

        #pragma unroll
        for (int k = 0; k < 32; k++) {
            float4 a4 = *(float4*)&AshT[k][r0];
            float4 b4 = *(float4*)&Bsh[k][c0];
            float a[4] = {a4.x, a4.y, a4.z, a4.w};
            float b[4] = {b4.x, b4.y, b4.z, b4.w};
            #pragma unroll
            for (int i = 0; i < 4; i++)
                #pragma unroll
                for (int j = 0; j < 4; j++)
                    acc[i][j] += a[i] * b[j];
        }
        __syncthreads();
    }

    float4 bi = *(const float4*)(bias + nb + c0);
    #pragma unroll
    for (int i = 0; i < 4; i++) {
        float4 o;
        o.x = acc[i][0] + bi.x;
        o.y = acc[i][1] + bi.y;
        o.z = acc[i][2] + bi.z;
        o.w = acc[i][3] + bi.w;
        *(float4*)(C + (size_t)(mb + r0 + i) * DM + nb + c0) = o;
    }
}

// ---------------------------------------------------------------------------
// Same GEMM but epilogue writes bf16 hi/lo split pair (for Q, K)
// ---------------------------------------------------------------------------
__global__ __launch_bounds__(256)
void gemm_bias_bf16out_kernel(const float* __restrict__ A, const float* __restrict__ W,
                              const float* __restrict__ bias,
                              unsigned short* __restrict__ Chi,
                              unsigned short* __restrict__ Clo) {
    __shared__ float AshT[32][68];
    __shared__ float Bsh[32][68];

    const int nb = blockIdx.x * 64;
    const int mb = blockIdx.y * 64;
    const int tx = threadIdx.x;
    const int tr = tx >> 4, tc = tx & 15;
    const int r0 = tr * 4, c0 = tc * 4;

    float acc[4][4] = {};

    for (int k0 = 0; k0 < DM; k0 += 32) {
        #pragma unroll
        for (int t = tx; t < 512; t += 256) {
            int r = t >> 3;
            int k4 = (t & 7) * 4;
            float4 a4 = *(const float4*)(A + (size_t)(mb + r) * DM + k0 + k4);
            AshT[k4 + 0][r] = a4.x;
            AshT[k4 + 1][r] = a4.y;
            AshT[k4 + 2][r] = a4.z;
            AshT[k4 + 3][r] = a4.w;
        }
        #pragma unroll
        for (int t = tx; t < 512; t += 256) {
            int k = t >> 4;
            int c4 = (t & 15) * 4;
            *(float4*)&Bsh[k][c4] = *(const float4*)(W + (size_t)(k0 + k) * DM + nb + c4);
        }
        __syncthreads();

        #pragma unroll
        for (int k = 0; k < 32; k++) {
            float4 a4 = *(float4*)&AshT[k][r0];
            float4 b4 = *(float4*)&Bsh[k][c0];
            float a[4] = {a4.x, a4.y, a4.z, a4.w};
            float b[4] = {b4.x, b4.y, b4.z, b4.w};
            #pragma unroll
            for (int i = 0; i < 4; i++)
                #pragma unroll
                for (int j = 0; j < 4; j++)
                    acc[i][j] += a[i] * b[j];
        }
        __syncthreads();
    }

    float4 bi = *(const float4*)(bias + nb + c0);
    #pragma unroll
    for (int i = 0; i < 4; i++) {
        float o[4];
        o[0] = acc[i][0] + bi.x;
        o[1] = acc[i][1] + bi.y;
        o[2] = acc[i][2] + bi.z;
        o[3] = acc[i][3] + bi.w;
        unsigned h01 = packbf(o[0], o[1]);
        unsigned h23 = packbf(o[2], o[3]);
        float r0f = o[0] - __uint_as_float(h01 << 16);
        float r1f = o[1] - __uint_as_float(h01 & 0xFFFF0000u);
        float r2f = o[2] - __uint_as_float(h23 << 16);
        float r3f = o[3] - __uint_as_float(h23 & 0xFFFF0000u);
        unsigned l01 = packbf(r0f, r1f);
        unsigned l23 = packbf(r2f, r3f);
        size_t off = (size_t)(mb + r0 + i) * DM + nb + c0;
        *(uint2*)(Chi + off) = make_uint2(h01, h23);
        *(uint2*)(Clo + off) = make_uint2(l01, l23);
    }
}

// ---------------------------------------------------------------------------
// Transpose + split V: g_v fp32 [b][n][D]  ->  g_vt{hi,lo} bf16 [b][h][d][n]
// ---------------------------------------------------------------------------
__global__ __launch_bounds__(256)
void transpose_v_kernel() {
    __shared__ float S[64][65];
    const int nbase = blockIdx.x * 64;
    const int h = blockIdx.y;
    const int b = blockIdx.z;
    const int tx = threadIdx.x;

    for (int t = tx; t < 1024; t += 256) {
        int n = t >> 4;
        int s4 = (t & 15) * 4;
        float4 v = *(const float4*)(g_v + (size_t)(b * NTOK + nbase + n) * DM + h * HD + s4);
        S[n][s4 + 0] = v.x;
        S[n][s4 + 1] = v.y;
        S[n][s4 + 2] = v.z;
        S[n][s4 + 3] = v.w;
    }
    __syncthreads();

    for (int t = tx; t < 1024; t += 256) {
        int d = t >> 4;
        int q4 = (t & 15) * 4;
        float v0 = S[q4 + 0][d], v1 = S[q4 + 1][d], v2 = S[q4 + 2][d], v3 = S[q4 + 3][d];
        unsigned h01 = packbf(v0, v1);
        unsigned h23 = packbf(v2, v3);
        float r0f = v0 - __uint_as_float(h01 << 16);
        float r1f = v1 - __uint_as_float(h01 & 0xFFFF0000u);
        float r2f = v2 - __uint_as_float(h23 << 16);
        float r3f = v3 - __uint_as_float(h23 & 0xFFFF0000u);
        unsigned l01 = packbf(r0f, r1f);
        unsigned l23 = packbf(r2f, r3f);
        size_t off = ((size_t)((b * NH + h) * HD + d)) * NTOK + nbase + q4;
        *(uint2*)(g_vthi + off) = make_uint2(h01, h23);
        *(uint2*)(g_vtlo + off) = make_uint2(l01, l23);
    }
}

// ---------------------------------------------------------------------------
// Flash attention with bf16-split tensor-core MMAs.
// Grid (NTOK/64, NH, BATCH), block = 128 (4 warps, 16 q-rows each).
// smem (u32 words, row stride 36 words = 72 bf16 -> conflict-free frags):
//   Qhi, Qlo, Khi, Klo, Vthi, Vtlo : each 64*36 words
// ---------------------------------------------------------------------------
#define SW_Q_HI 0
#define SW_Q_LO 2304
#define SW_K_HI 4608
#define SW_K_LO 6912
#define SW_V_HI 9216
#define SW_V_LO 11520
#define ATTN_SMEM_BYTES (13824 * 4)

__global__ __launch_bounds__(128)
void attn_mma_kernel(const float* __restrict__ adj) {
    extern __shared__ unsigned smw[];

    const int qt = blockIdx.x;
    const int h  = blockIdx.y;
    const int b  = blockIdx.z;
    const int tid  = threadIdx.x;
    const int wid  = tid >> 5;
    const int lane = tid & 31;
    const int qbase = qt * 64;
    const int wr0 = wid * 16;
    const int qr = lane >> 2;   // row within 8-group
    const int qc = lane & 3;    // col-pair selector

    // ---- load Q tile (hi/lo) into smem, once ----
    for (int t = tid; t < 512; t += 128) {
        int r = t >> 3, s = t & 7;
        size_t g = (size_t)(b * NTOK + qbase + r) * DM + h * HD + s * 8;
        *(uint4*)&smw[SW_Q_HI + r * 36 + s * 4] = *(const uint4*)(g_qhi + g);
        *(uint4*)&smw[SW_Q_LO + r * 36 + s * 4] = *(const uint4*)(g_qlo + g);
    }

    float oacc[8][4];
    #pragma unroll
    for (int nt = 0; nt < 8; nt++)
        #pragma unroll
        for (int j = 0; j < 4; j++) oacc[nt][j] = 0.0f;

    float mA = -1e30f, mB = -1e30f, lA = 0.0f, lB = 0.0f;

    const float* adjA = adj + (size_t)(qbase + wr0 + qr) * NTOK;
    const float* adjB = adjA + (size_t)8 * NTOK;

    for (int kt = 0; kt < NTOK / 64; kt++) {
        const int kbase = kt * 64;
        __syncthreads();
        // ---- load K (hi/lo) and V^T (hi/lo) tiles ----
        for (int t = tid; t < 512; t += 128) {
            int r = t >> 3, s = t & 7;
            size_t gk = (size_t)(b * NTOK + kbase + r) * DM + h * HD + s * 8;
            *(uint4*)&smw[SW_K_HI + r * 36 + s * 4] = *(const uint4*)(g_khi + gk);
            *(uint4*)&smw[SW_K_LO + r * 36 + s * 4] = *(const uint4*)(g_klo + gk);
            size_t gv = ((size_t)((b * NH + h) * HD + r)) * NTOK + kbase + s * 8;
            *(uint4*)&smw[SW_V_HI + r * 36 + s * 4] = *(const uint4*)(g_vthi + gv);
            *(uint4*)&smw[SW_V_LO + r * 36 + s * 4] = *(const uint4*)(g_vtlo + gv);
        }
        __syncthreads();

        // ---- S = Q @ K^T (bf16 split: hihi + hilo + lohi) ----
        float s_[8][4];
        #pragma unroll
        for (int nt = 0; nt < 8; nt++)
            #pragma unroll
            for (int j = 0; j < 4; j++) s_[nt][j] = 0.0f;

        #pragma unroll
        for (int kc = 0; kc < 4; kc++) {
            const int abase = (wr0 + qr) * 36 + kc * 8 + qc;
            unsigned ah0 = smw[SW_Q_HI + abase];
            unsigned ah1 = smw[SW_Q_HI + abase + 8 * 36];
            unsigned ah2 = smw[SW_Q_HI + abase + 4];
            unsigned ah3 = smw[SW_Q_HI + abase + 8 * 36 + 4];
            unsigned al0 = smw[SW_Q_LO + abase];
            unsigned al1 = smw[SW_Q_LO + abase + 8 * 36];
            unsigned al2 = smw[SW_Q_LO + abase + 4];
            unsigned al3 = smw[SW_Q_LO + abase + 8 * 36 + 4];
            #pragma unroll
            for (int nt = 0; nt < 8; nt++) {
                const int bbase = (nt * 8 + qr) * 36 + kc * 8 + qc;
                unsigned bh0 = smw[SW_K_HI + bbase];
                unsigned bh1 = smw[SW_K_HI + bbase + 4];
                unsigned bl0 = smw[SW_K_LO + bbase];
                unsigned bl1 = smw[SW_K_LO + bbase + 4];
                mma16816(s_[nt], ah0, ah1, ah2, ah3, bh0, bh1);
                mma16816(s_[nt], ah0, ah1, ah2, ah3, bl0, bl1);
                mma16816(s_[nt], al0, al1, al2, al3, bh0, bh1);
            }
        }

        // ---- scale + adjacency mask + online softmax ----
        float tmaxA = -1e30f, tmaxB = -1e30f;
        #pragma unroll
        for (int nt = 0; nt < 8; nt++) {
            int col = kbase + nt * 8 + qc * 2;
            float2 a2 = *(const float2*)(adjA + col);
            float2 b2 = *(const float2*)(adjB + col);
            s_[nt][0] = s_[nt][0] * 0.125f + (a2.x - 1.0f) * 1e9f;
            s_[nt][1] = s_[nt][1] * 0.125f + (a2.y - 1.0f) * 1e9f;
            s_[nt][2] = s_[nt][2] * 0.125f + (b2.x - 1.0f) * 1e9f;
            s_[nt][3] = s_[nt][3] * 0.125f + (b2.y - 1.0f) * 1e9f;
            tmaxA = fmaxf(tmaxA, fmaxf(s_[nt][0], s_[nt][1]));
            tmaxB = fmaxf(tmaxB, fmaxf(s_[nt][2], s_[nt][3]));
        }
        tmaxA = fmaxf(tmaxA, __shfl_xor_sync(0xffffffffu, tmaxA, 1));
        tmaxA = fmaxf(tmaxA, __shfl_xor_sync(0xffffffffu, tmaxA, 2));
        tmaxB = fmaxf(tmaxB, __shfl_xor_sync(0xffffffffu, tmaxB, 1));
        tmaxB = fmaxf(tmaxB, __shfl_xor_sync(0xffffffffu, tmaxB, 2));

        float mnA = fmaxf(mA, tmaxA);
        float mnB = fmaxf(mB, tmaxB);
        float scA = __expf(mA - mnA);
        float scB = __expf(mB - mnB);
        mA = mnA; mB = mnB;

        float rsA = 0.0f, rsB = 0.0f;
        #pragma unroll
        for (int nt = 0; nt < 8; nt++) {
            s_[nt][0] = __expf(s_[nt][0] - mnA); rsA += s_[nt][0];
            s_[nt][1] = __expf(s_[nt][1] - mnA); rsA += s_[nt][1];
            s_[nt][2] = __expf(s_[nt][2] - mnB); rsB += s_[nt][2];
            s_[nt][3] = __expf(s_[nt][3] - mnB); rsB += s_[nt][3];
        }
        rsA += __shfl_xor_sync(0xffffffffu, rsA, 1);
        rsA += __shfl_xor_sync(0xffffffffu, rsA, 2);
        rsB += __shfl_xor_sync(0xffffffffu, rsB, 1);
        rsB += __shfl_xor_sync(0xffffffffu, rsB, 2);
        lA = lA * scA + rsA;
        lB = lB * scB + rsB;

        #pragma unroll
        for (int nt = 0; nt < 8; nt++) {
            oacc[nt][0] *= scA;
            oacc[nt][1] *= scA;
            oacc[nt][2] *= scB;
            oacc[nt][3] *= scB;
        }

        // ---- O += P @ V  (P repacked from S frags in registers) ----
        #pragma unroll
        for (int kc = 0; kc < 4; kc++) {
            const int n0 = 2 * kc, n1 = 2 * kc + 1;
            unsigned ph0 = packbf(s_[n0][0], s_[n0][1]);
            unsigned ph1 = packbf(s_[n0][2], s_[n0][3]);
            unsigned ph2 = packbf(s_[n1][0], s_[n1][1]);
            unsigned ph3 = packbf(s_[n1][2], s_[n1][3]);
            unsigned pl0 = packbf(s_[n0][0] - __uint_as_float(ph0 << 16),
                                  s_[n0][1] - __uint_as_float(ph0 & 0xFFFF0000u));
            unsigned pl1 = packbf(s_[n0][2] - __uint_as_float(ph1 << 16),
                                  s_[n0][3] - __uint_as_float(ph1 & 0xFFFF0000u));
            unsigned pl2 = packbf(s_[n1][0] - __uint_as_float(ph2 << 16),
                                  s_[n1][1] - __uint_as_float(ph2 & 0xFFFF0000u));
            unsigned pl3 = packbf(s_[n1][2] - __uint_as_float(ph3 << 16),
                                  s_[n1][3] - __uint_as_float(ph3 & 0xFFFF0000u));
            #pragma unroll
            for (int nt = 0; nt < 8; nt++) {
                const int bbase = (nt * 8 + qr) * 36 + kc * 8 + qc;
                unsigned bh0 = smw[SW_V_HI + bbase];
                unsigned bh1 = smw[SW_V_HI + bbase + 4];
                unsigned bl0 = smw[SW_V_LO + bbase];
                unsigned bl1 = smw[SW_V_LO + bbase + 4];
                mma16816(oacc[nt], ph0, ph1, ph2, ph3, bh0, bh1);
                mma16816(oacc[nt], ph0, ph1, ph2, ph3, bl0, bl1);
                mma16816(oacc[nt], pl0, pl1, pl2, pl3, bh0, bh1);
            }
        }
    }

    // ---- epilogue: normalize + store fp32 ----
    float invA = 1.0f / lA;
    float invB = 1.0f / lB;
    float* outA = g_ao + (size_t)(b * NTOK + qbase + wr0 + qr) * DM + h * HD;
    float* outB = outA + (size_t)8 * DM;
    #pragma unroll
    for (int nt = 0; nt < 8; nt++) {
        int col = nt * 8 + qc * 2;
        *(float2*)(outA + col) = make_float2(oacc[nt][0] * invA, oacc[nt][1] * invA);
        *(float2*)(outB + col) = make_float2(oacc[nt][2] * invB, oacc[nt][3] * invB);
    }
}

// ---------------------------------------------------------------------------
extern "C" void kernel_launch(void* const* d_in, const int* in_sizes, int n_in,
                              void* d_out, int out_size) {
    const float* x   = (const float*)d_in[0];
    const float* adj = (const float*)d_in[1];
    const float* Wq  = (const float*)d_in[2];
    const float* bq  = (const float*)d_in[3];
    const float* Wk  = (const float*)d_in[4];
    const float* bk  = (const float*)d_in[5];
    const float* Wv  = (const float*)d_in[6];
    const float* bv  = (const float*)d_in[7];
    const float* Wo  = (const float*)d_in[8];
    const float* bo  = (const float*)d_in[9];
    float* out = (float*)d_out;

    float *pv, *pao;
    unsigned short *pqhi, *pqlo, *pkhi, *pklo;
    cudaGetSymbolAddress((void**)&pv,   g_v);
    cudaGetSymbolAddress((void**)&pao,  g_ao);
    cudaGetSymbolAddress((void**)&pqhi, g_qhi);
    cudaGetSymbolAddress((void**)&pqlo, g_qlo);
    cudaGetSymbolAddress((void**)&pkhi, g_khi);
    cudaGetSymbolAddress((void**)&pklo, g_klo);

    dim3 gg(DM / 64, BATCH * NTOK / 64);
    gemm_bias_bf16out_kernel<<<gg, 256>>>(x, Wq, bq, pqhi, pqlo);
    gemm_bias_bf16out_kernel<<<gg, 256>>>(x, Wk, bk, pkhi, pklo);
    gemm_bias_kernel<<<gg, 256>>>(x, Wv, bv, pv);

    transpose_v_kernel<<<dim3(NTOK / 64, NH, BATCH), 256>>>();

    cudaFuncSetAttribute(attn_mma_kernel, cudaFuncAttributeMaxDynamicSharedMemorySize,
                         ATTN_SMEM_BYTES);
    attn_mma_kernel<<<dim3(NTOK / 64, NH, BATCH), 128, ATTN_SMEM_BYTES>>>(adj);

    gemm_bias_kernel<<<gg, 256>>>(pao, Wo, bo, out);
}

// round 8
// speedup vs baseline: 2.3453x; 1.4478x over previous
#include <cuda_runtime.h>
#include <cuda_bf16.h>

#define BATCH 4
#define NTOK 2048
#define DM 512
#define NH 8
#define HD 64
#define MROWS (BATCH * NTOK)   // 8192

// ---------------- scratch (device globals; no allocations allowed) ----------
__device__ unsigned short g_xhi [MROWS * DM];
__device__ unsigned short g_xlo [MROWS * DM];
__device__ unsigned short g_qhi [MROWS * DM];
__device__ unsigned short g_qlo [MROWS * DM];
__device__ unsigned short g_khi [MROWS * DM];
__device__ unsigned short g_klo [MROWS * DM];
__device__ unsigned short g_vthi[MROWS * DM];   // V^T bf16 [b][h][d][n]
__device__ unsigned short g_vtlo[MROWS * DM];
__device__ unsigned short g_aohi[MROWS * DM];
__device__ unsigned short g_aolo[MROWS * DM];
__device__ unsigned short g_wthi[4 * DM * DM];  // W^T [which][n][k]
__device__ unsigned short g_wtlo[4 * DM * DM];

// ---------------- helpers ---------------------------------------------------
__device__ __forceinline__ unsigned packbf(float lo, float hi) {
    unsigned r;
    asm("cvt.rn.bf16x2.f32 %0, %1, %2;" : "=r"(r) : "f"(hi), "f"(lo));
    return r;  // low 16 bits = bf16(lo), high 16 = bf16(hi)
}

// split pair (v0,v1) -> hi word + lo word
__device__ __forceinline__ void split2(float v0, float v1, unsigned& h, unsigned& l) {
    h = packbf(v0, v1);
    float r0 = v0 - __uint_as_float(h << 16);
    float r1 = v1 - __uint_as_float(h & 0xFFFF0000u);
    l = packbf(r0, r1);
}

__device__ __forceinline__ void mma16816(float* c,
                                         unsigned a0, unsigned a1, unsigned a2, unsigned a3,
                                         unsigned b0, unsigned b1) {
    asm volatile(
        "mma.sync.aligned.m16n8k16.row.col.f32.bf16.bf16.f32 "
        "{%0,%1,%2,%3}, {%4,%5,%6,%7}, {%8,%9}, {%0,%1,%2,%3};"
        : "+f"(c[0]), "+f"(c[1]), "+f"(c[2]), "+f"(c[3])
        : "r"(a0), "r"(a1), "r"(a2), "r"(a3), "r"(b0), "r"(b1));
}

// ---------------------------------------------------------------------------
// split_x: fp32 [MROWS*DM] -> bf16 hi/lo
// ---------------------------------------------------------------------------
__global__ __launch_bounds__(256)
void split_x_kernel(const float* __restrict__ X) {
    size_t i = ((size_t)blockIdx.x * 256 + threadIdx.x) * 4;
    float4 v = *(const float4*)(X + i);
    unsigned h01, l01, h23, l23;
    split2(v.x, v.y, h01, l01);
    split2(v.z, v.w, h23, l23);
    *(uint2*)(g_xhi + i) = make_uint2(h01, h23);
    *(uint2*)(g_xlo + i) = make_uint2(l01, l23);
}

// ---------------------------------------------------------------------------
// split_wT: W [k][n] fp32 -> W^T [n][k] bf16 hi/lo (into slot `which`)
// ---------------------------------------------------------------------------
__global__ __launch_bounds__(256)
void split_wT_kernel(const float* __restrict__ W, int which) {
    __shared__ float S[32][33];
    const int nb = blockIdx.x * 32, kb = blockIdx.y * 32;
    const int c = threadIdx.x & 31, r8 = threadIdx.x >> 5;
    #pragma unroll
    for (int i = 0; i < 4; i++) {
        int r = r8 + i * 8;
        S[r][c] = W[(size_t)(kb + r) * DM + nb + c];
    }
    __syncthreads();
    unsigned short* Thi = g_wthi + (size_t)which * DM * DM;
    unsigned short* Tlo = g_wtlo + (size_t)which * DM * DM;
    #pragma unroll
    for (int i = 0; i < 4; i++) {
        int n = r8 + i * 8;
        float v = S[c][n];                       // = W[kb+c][nb+n]
        __nv_bfloat16 hb = __float2bfloat16(v);
        float hv = __bfloat162float(hb);
        __nv_bfloat16 lb = __float2bfloat16(v - hv);
        size_t off = (size_t)(nb + n) * DM + kb + c;
        Thi[off] = *(unsigned short*)&hb;
        Tlo[off] = *(unsigned short*)&lb;
    }
}

// ---------------------------------------------------------------------------
// bf16-split MMA GEMM:  C[M=8192, N=512] = A @ W^T_layout + bias
// Tile 128(M) x 64(N), BK=64. 8 warps (4x2), warp tile 32x32.
// smem words (stride 36/row, conflict-free fragment loads):
//   Ahi[128*36] Alo[128*36] Bhi[64*36] Blo[64*36] = 13824 words (55296 B)
// MODE 0: fp32 out + bias (output proj)
// MODE 1: bf16 hi/lo split out (Q, K)
// MODE 2: transposed split out -> [b][h][d][n] (V)
// ---------------------------------------------------------------------------
#define GA_HI 0
#define GA_LO 4608
#define GB_HI 9216
#define GB_LO 11520
#define GEMM_SMEM_BYTES (13824 * 4)

template <int MODE>
__global__ __launch_bounds__(256)
void mma_gemm_kernel(const unsigned short* __restrict__ Ahi,
                     const unsigned short* __restrict__ Alo,
                     const unsigned short* __restrict__ Bhi,
                     const unsigned short* __restrict__ Blo,
                     const float* __restrict__ bias,
                     float* __restrict__ Cf,
                     unsigned short* __restrict__ Chi,
                     unsigned short* __restrict__ Clo) {
    extern __shared__ unsigned sw[];

    const int nb = blockIdx.x * 64;
    const int mb = blockIdx.y * 128;
    const int tid = threadIdx.x;
    const int wid = tid >> 5, lane = tid & 31;
    const int wm = wid >> 1, wn = wid & 1;
    const int qr = lane >> 2, qc = lane & 3;

    float acc[2][4][4];
    #pragma unroll
    for (int mf = 0; mf < 2; mf++)
        #pragma unroll
        for (int nf = 0; nf < 4; nf++)
            #pragma unroll
            for (int j = 0; j < 4; j++) acc[mf][nf][j] = 0.0f;

    for (int k0 = 0; k0 < DM; k0 += 64) {
        __syncthreads();
        // A tile: 128 rows x 64 bf16 (32 words) -> 8 uint4/row
        #pragma unroll
        for (int t = tid; t < 1024; t += 256) {
            int r = t >> 3, s = t & 7;
            size_t g = (size_t)(mb + r) * DM + k0 + s * 8;
            *(uint4*)&sw[GA_HI + r * 36 + s * 4] = *(const uint4*)(Ahi + g);
            *(uint4*)&sw[GA_LO + r * 36 + s * 4] = *(const uint4*)(Alo + g);
        }
        // B tile: 64 rows (n) x 64 bf16 (k)
        #pragma unroll
        for (int t = tid; t < 512; t += 256) {
            int r = t >> 3, s = t & 7;
            size_t g = (size_t)(nb + r) * DM + k0 + s * 8;
            *(uint4*)&sw[GB_HI + r * 36 + s * 4] = *(const uint4*)(Bhi + g);
            *(uint4*)&sw[GB_LO + r * 36 + s * 4] = *(const uint4*)(Blo + g);
        }
        __syncthreads();

        #pragma unroll
        for (int ks = 0; ks < 4; ks++) {
            unsigned ah[2][4], al[2][4];
            #pragma unroll
            for (int mf = 0; mf < 2; mf++) {
                int ab = (wm * 32 + mf * 16 + qr) * 36 + ks * 8 + qc;
                ah[mf][0] = sw[GA_HI + ab];
                ah[mf][1] = sw[GA_HI + ab + 8 * 36];
                ah[mf][2] = sw[GA_HI + ab + 4];
                ah[mf][3] = sw[GA_HI + ab + 8 * 36 + 4];
                al[mf][0] = sw[GA_LO + ab];
                al[mf][1] = sw[GA_LO + ab + 8 * 36];
                al[mf][2] = sw[GA_LO + ab + 4];
                al[mf][3] = sw[GA_LO + ab + 8 * 36 + 4];
            }
            #pragma unroll
            for (int nf = 0; nf < 4; nf++) {
                int bb = (wn * 32 + nf * 8 + qr) * 36 + ks * 8 + qc;
                unsigned bh0 = sw[GB_HI + bb], bh1 = sw[GB_HI + bb + 4];
                unsigned bl0 = sw[GB_LO + bb], bl1 = sw[GB_LO + bb + 4];
                #pragma unroll
                for (int mf = 0; mf < 2; mf++) {
                    mma16816(acc[mf][nf], ah[mf][0], ah[mf][1], ah[mf][2], ah[mf][3], bh0, bh1);
                    mma16816(acc[mf][nf], ah[mf][0], ah[mf][1], ah[mf][2], ah[mf][3], bl0, bl1);
                    mma16816(acc[mf][nf], al[mf][0], al[mf][1], al[mf][2], al[mf][3], bh0, bh1);
                }
            }
        }
    }

    // ---- epilogue ----
    if (MODE == 0 || MODE == 1) {
        #pragma unroll
        for (int mf = 0; mf < 2; mf++) {
            #pragma unroll
            for (int nf = 0; nf < 4; nf++) {
                int col = wn * 32 + nf * 8 + qc * 2;
                float2 bi = *(const float2*)(bias + nb + col);
                int r0 = mb + wm * 32 + mf * 16 + qr;
                float v0 = acc[mf][nf][0] + bi.x;
                float v1 = acc[mf][nf][1] + bi.y;
                float v2 = acc[mf][nf][2] + bi.x;
                float v3 = acc[mf][nf][3] + bi.y;
                if (MODE == 0) {
                    *(float2*)(Cf + (size_t)r0 * DM + nb + col) = make_float2(v0, v1);
                    *(float2*)(Cf + (size_t)(r0 + 8) * DM + nb + col) = make_float2(v2, v3);
                } else {
                    unsigned h, l;
                    split2(v0, v1, h, l);
                    *(unsigned*)(Chi + (size_t)r0 * DM + nb + col) = h;
                    *(unsigned*)(Clo + (size_t)r0 * DM + nb + col) = l;
                    split2(v2, v3, h, l);
                    *(unsigned*)(Chi + (size_t)(r0 + 8) * DM + nb + col) = h;
                    *(unsigned*)(Clo + (size_t)(r0 + 8) * DM + nb + col) = l;
                }
            }
        }
    } else {
        // MODE 2: transpose 128(token) x 64(d) tile via smem, store [b][h][d][n]
        __syncthreads();
        float* T = (float*)sw;  // T[d][token], stride 132, 64*132 floats
        #pragma unroll
        for (int mf = 0; mf < 2; mf++) {
            #pragma unroll
            for (int nf = 0; nf < 4; nf++) {
                int c = wn * 32 + nf * 8 + qc * 2;
                float2 bi = *(const float2*)(bias + nb + c);
                int r = wm * 32 + mf * 16 + qr;
                T[(c + 0) * 132 + r]     = acc[mf][nf][0] + bi.x;
                T[(c + 1) * 132 + r]     = acc[mf][nf][1] + bi.y;
                T[(c + 0) * 132 + r + 8] = acc[mf][nf][2] + bi.x;
                T[(c + 1) * 132 + r + 8] = acc[mf][nf][3] + bi.y;
            }
        }
        __syncthreads();
        const int b  = mb >> 11;        // mb / NTOK
        const int n0 = mb & (NTOK - 1);
        const int h  = nb >> 6;
        #pragma unroll
        for (int t = tid; t < 2048; t += 256) {
            int dl = t >> 5;
            int r4 = (t & 31) * 4;
            float v0 = T[dl * 132 + r4 + 0];
            float v1 = T[dl * 132 + r4 + 1];
            float v2 = T[dl * 132 + r4 + 2];
            float v3 = T[dl * 132 + r4 + 3];
            unsigned h01, l01, h23, l23;
            split2(v0, v1, h01, l01);
            split2(v2, v3, h23, l23);
            size_t off = ((size_t)((b * NH + h) * HD + dl)) * NTOK + n0 + r4;
            *(uint2*)(Chi + off) = make_uint2(h01, h23);
            *(uint2*)(Clo + off) = make_uint2(l01, l23);
        }
    }
}

// ---------------------------------------------------------------------------
// Flash attention with bf16-split tensor-core MMAs (as R7) —
// epilogue now writes AO as bf16 hi/lo split for the output GEMM.
// ---------------------------------------------------------------------------
#define SW_Q_HI 0
#define SW_Q_LO 2304
#define SW_K_HI 4608
#define SW_K_LO 6912
#define SW_V_HI 9216
#define SW_V_LO 11520
#define ATTN_SMEM_BYTES (13824 * 4)

__global__ __launch_bounds__(128)
void attn_mma_kernel(const float* __restrict__ adj) {
    extern __shared__ unsigned smw[];

    const int qt = blockIdx.x;
    const int h  = blockIdx.y;
    const int b  = blockIdx.z;
    const int tid  = threadIdx.x;
    const int wid  = tid >> 5;
    const int lane = tid & 31;
    const int qbase = qt * 64;
    const int wr0 = wid * 16;
    const int qr = lane >> 2;
    const int qc = lane & 3;

    for (int t = tid; t < 512; t += 128) {
        int r = t >> 3, s = t & 7;
        size_t g = (size_t)(b * NTOK + qbase + r) * DM + h * HD + s * 8;
        *(uint4*)&smw[SW_Q_HI + r * 36 + s * 4] = *(const uint4*)(g_qhi + g);
        *(uint4*)&smw[SW_Q_LO + r * 36 + s * 4] = *(const uint4*)(g_qlo + g);
    }

    float oacc[8][4];
    #pragma unroll
    for (int nt = 0; nt < 8; nt++)
        #pragma unroll
        for (int j = 0; j < 4; j++) oacc[nt][j] = 0.0f;

    float mA = -1e30f, mB = -1e30f, lA = 0.0f, lB = 0.0f;

    const float* adjA = adj + (size_t)(qbase + wr0 + qr) * NTOK;
    const float* adjB = adjA + (size_t)8 * NTOK;

    for (int kt = 0; kt < NTOK / 64; kt++) {
        const int kbase = kt * 64;
        __syncthreads();
        for (int t = tid; t < 512; t += 128) {
            int r = t >> 3, s = t & 7;
            size_t gk = (size_t)(b * NTOK + kbase + r) * DM + h * HD + s * 8;
            *(uint4*)&smw[SW_K_HI + r * 36 + s * 4] = *(const uint4*)(g_khi + gk);
            *(uint4*)&smw[SW_K_LO + r * 36 + s * 4] = *(const uint4*)(g_klo + gk);
            size_t gv = ((size_t)((b * NH + h) * HD + r)) * NTOK + kbase + s * 8;
            *(uint4*)&smw[SW_V_HI + r * 36 + s * 4] = *(const uint4*)(g_vthi + gv);
            *(uint4*)&smw[SW_V_LO + r * 36 + s * 4] = *(const uint4*)(g_vtlo + gv);
        }
        __syncthreads();

        float s_[8][4];
        #pragma unroll
        for (int nt = 0; nt < 8; nt++)
            #pragma unroll
            for (int j = 0; j < 4; j++) s_[nt][j] = 0.0f;

        #pragma unroll
        for (int kc = 0; kc < 4; kc++) {
            const int abase = (wr0 + qr) * 36 + kc * 8 + qc;
            unsigned ah0 = smw[SW_Q_HI + abase];
            unsigned ah1 = smw[SW_Q_HI + abase + 8 * 36];
            unsigned ah2 = smw[SW_Q_HI + abase + 4];
            unsigned ah3 = smw[SW_Q_HI + abase + 8 * 36 + 4];
            unsigned al0 = smw[SW_Q_LO + abase];
            unsigned al1 = smw[SW_Q_LO + abase + 8 * 36];
            unsigned al2 = smw[SW_Q_LO + abase + 4];
            unsigned al3 = smw[SW_Q_LO + abase + 8 * 36 + 4];
            #pragma unroll
            for (int nt = 0; nt < 8; nt++) {
                const int bbase = (nt * 8 + qr) * 36 + kc * 8 + qc;
                unsigned bh0 = smw[SW_K_HI + bbase];
                unsigned bh1 = smw[SW_K_HI + bbase + 4];
                unsigned bl0 = smw[SW_K_LO + bbase];
                unsigned bl1 = smw[SW_K_LO + bbase + 4];
                mma16816(s_[nt], ah0, ah1, ah2, ah3, bh0, bh1);
                mma16816(s_[nt], ah0, ah1, ah2, ah3, bl0, bl1);
                mma16816(s_[nt], al0, al1, al2, al3, bh0, bh1);
            }
        }

        float tmaxA = -1e30f, tmaxB = -1e30f;
        #pragma unroll
        for (int nt = 0; nt < 8; nt++) {
            int col = kbase + nt * 8 + qc * 2;
            float2 a2 = *(const float2*)(adjA + col);
            float2 b2 = *(const float2*)(adjB + col);
            s_[nt][0] = s_[nt][0] * 0.125f + (a2.x - 1.0f) * 1e9f;
            s_[nt][1] = s_[nt][1] * 0.125f + (a2.y - 1.0f) * 1e9f;
            s_[nt][2] = s_[nt][2] * 0.125f + (b2.x - 1.0f) * 1e9f;
            s_[nt][3] = s_[nt][3] * 0.125f + (b2.y - 1.0f) * 1e9f;
            tmaxA = fmaxf(tmaxA, fmaxf(s_[nt][0], s_[nt][1]));
            tmaxB = fmaxf(tmaxB, fmaxf(s_[nt][2], s_[nt][3]));
        }
        tmaxA = fmaxf(tmaxA, __shfl_xor_sync(0xffffffffu, tmaxA, 1));
        tmaxA = fmaxf(tmaxA, __shfl_xor_sync(0xffffffffu, tmaxA, 2));
        tmaxB = fmaxf(tmaxB, __shfl_xor_sync(0xffffffffu, tmaxB, 1));
        tmaxB = fmaxf(tmaxB, __shfl_xor_sync(0xffffffffu, tmaxB, 2));

        float mnA = fmaxf(mA, tmaxA);
        float mnB = fmaxf(mB, tmaxB);
        float scA = __expf(mA - mnA);
        float scB = __expf(mB - mnB);
        mA = mnA; mB = mnB;

        float rsA = 0.0f, rsB = 0.0f;
        #pragma unroll
        for (int nt = 0; nt < 8; nt++) {
            s_[nt][0] = __expf(s_[nt][0] - mnA); rsA += s_[nt][0];
            s_[nt][1] = __expf(s_[nt][1] - mnA); rsA += s_[nt][1];
            s_[nt][2] = __expf(s_[nt][2] - mnB); rsB += s_[nt][2];
            s_[nt][3] = __expf(s_[nt][3] - mnB); rsB += s_[nt][3];
        }
        rsA += __shfl_xor_sync(0xffffffffu, rsA, 1);
        rsA += __shfl_xor_sync(0xffffffffu, rsA, 2);
        rsB += __shfl_xor_sync(0xffffffffu, rsB, 1);
        rsB += __shfl_xor_sync(0xffffffffu, rsB, 2);
        lA = lA * scA + rsA;
        lB = lB * scB + rsB;

        #pragma unroll
        for (int nt = 0; nt < 8; nt++) {
            oacc[nt][0] *= scA;
            oacc[nt][1] *= scA;
            oacc[nt][2] *= scB;
            oacc[nt][3] *= scB;
        }

        #pragma unroll
        for (int kc = 0; kc < 4; kc++) {
            const int n0 = 2 * kc, n1 = 2 * kc + 1;
            unsigned ph0, pl0, ph1, pl1, ph2, pl2, ph3, pl3;
            split2(s_[n0][0], s_[n0][1], ph0, pl0);
            split2(s_[n0][2], s_[n0][3], ph1, pl1);
            split2(s_[n1][0], s_[n1][1], ph2, pl2);
            split2(s_[n1][2], s_[n1][3], ph3, pl3);
            #pragma unroll
            for (int nt = 0; nt < 8; nt++) {
                const int bbase = (nt * 8 + qr) * 36 + kc * 8 + qc;
                unsigned bh0 = smw[SW_V_HI + bbase];
                unsigned bh1 = smw[SW_V_HI + bbase + 4];
                unsigned bl0 = smw[SW_V_LO + bbase];
                unsigned bl1 = smw[SW_V_LO + bbase + 4];
                mma16816(oacc[nt], ph0, ph1, ph2, ph3, bh0, bh1);
                mma16816(oacc[nt], ph0, ph1, ph2, ph3, bl0, bl1);
                mma16816(oacc[nt], pl0, pl1, pl2, pl3, bh0, bh1);
            }
        }
    }

    // ---- epilogue: normalize + split-store AO (bf16 hi/lo) ----
    float invA = 1.0f / lA;
    float invB = 1.0f / lB;
    size_t offA = (size_t)(b * NTOK + qbase + wr0 + qr) * DM + h * HD;
    size_t offB = offA + (size_t)8 * DM;
    #pragma unroll
    for (int nt = 0; nt < 8; nt++) {
        int col = nt * 8 + qc * 2;
        unsigned hA, lAv, hB, lBv;
        split2(oacc[nt][0] * invA, oacc[nt][1] * invA, hA, lAv);
        split2(oacc[nt][2] * invB, oacc[nt][3] * invB, hB, lBv);
        *(unsigned*)(g_aohi + offA + col) = hA;
        *(unsigned*)(g_aolo + offA + col) = lAv;
        *(unsigned*)(g_aohi + offB + col) = hB;
        *(unsigned*)(g_aolo + offB + col) = lBv;
    }
}

// ---------------------------------------------------------------------------
extern "C" void kernel_launch(void* const* d_in, const int* in_sizes, int n_in,
                              void* d_out, int out_size) {
    const float* x   = (const float*)d_in[0];
    const float* adj = (const float*)d_in[1];
    const float* Wq  = (const float*)d_in[2];
    const float* bq  = (const float*)d_in[3];
    const float* Wk  = (const float*)d_in[4];
    const float* bk  = (const float*)d_in[5];
    const float* Wv  = (const float*)d_in[6];
    const float* bv  = (const float*)d_in[7];
    const float* Wo  = (const float*)d_in[8];
    const float* bo  = (const float*)d_in[9];
    float* out = (float*)d_out;

    unsigned short *xhi, *xlo, *qhi, *qlo, *khi, *klo, *vthi, *vtlo, *aohi, *aolo, *wthi, *wtlo;
    cudaGetSymbolAddress((void**)&xhi,  g_xhi);
    cudaGetSymbolAddress((void**)&xlo,  g_xlo);
    cudaGetSymbolAddress((void**)&qhi,  g_qhi);
    cudaGetSymbolAddress((void**)&qlo,  g_qlo);
    cudaGetSymbolAddress((void**)&khi,  g_khi);
    cudaGetSymbolAddress((void**)&klo,  g_klo);
    cudaGetSymbolAddress((void**)&vthi, g_vthi);
    cudaGetSymbolAddress((void**)&vtlo, g_vtlo);
    cudaGetSymbolAddress((void**)&aohi, g_aohi);
    cudaGetSymbolAddress((void**)&aolo, g_aolo);
    cudaGetSymbolAddress((void**)&wthi, g_wthi);
    cudaGetSymbolAddress((void**)&wtlo, g_wtlo);

    // 1) split inputs / weights
    split_x_kernel<<<(MROWS * DM) / (256 * 4), 256>>>(x);
    dim3 wg(DM / 32, DM / 32);
    split_wT_kernel<<<wg, 256>>>(Wq, 0);
    split_wT_kernel<<<wg, 256>>>(Wk, 1);
    split_wT_kernel<<<wg, 256>>>(Wv, 2);
    split_wT_kernel<<<wg, 256>>>(Wo, 3);

    // 2) projection GEMMs (tensor core)
    cudaFuncSetAttribute(mma_gemm_kernel<0>, cudaFuncAttributeMaxDynamicSharedMemorySize, GEMM_SMEM_BYTES);
    cudaFuncSetAttribute(mma_gemm_kernel<1>, cudaFuncAttributeMaxDynamicSharedMemorySize, GEMM_SMEM_BYTES);
    cudaFuncSetAttribute(mma_gemm_kernel<2>, cudaFuncAttributeMaxDynamicSharedMemorySize, GEMM_SMEM_BYTES);
    dim3 gg(DM / 64, MROWS / 128);  // (8, 64)
    mma_gemm_kernel<1><<<gg, 256, GEMM_SMEM_BYTES>>>(xhi, xlo, wthi + 0 * DM * DM, wtlo + 0 * DM * DM,
                                                     bq, nullptr, qhi, qlo);
    mma_gemm_kernel<1><<<gg, 256, GEMM_SMEM_BYTES>>>(xhi, xlo, wthi + 1 * DM * DM, wtlo + 1 * DM * DM,
                                                     bk, nullptr, khi, klo);
    mma_gemm_kernel<2><<<gg, 256, GEMM_SMEM_BYTES>>>(xhi, xlo, wthi + 2 * DM * DM, wtlo + 2 * DM * DM,
                                                     bv, nullptr, vthi, vtlo);

    // 3) attention
    cudaFuncSetAttribute(attn_mma_kernel, cudaFuncAttributeMaxDynamicSharedMemorySize, ATTN_SMEM_BYTES);
    attn_mma_kernel<<<dim3(NTOK / 64, NH, BATCH), 128, ATTN_SMEM_BYTES>>>(adj);

    // 4) output projection
    mma_gemm_kernel<0><<<gg, 256, GEMM_SMEM_BYTES>>>(aohi, aolo, wthi + 3 * DM * DM, wtlo + 3 * DM * DM,
                                                     bo, out, nullptr, nullptr);
}